// round 6
// baseline (speedup 1.0000x reference)
#include <cuda_runtime.h>
#include <stdint.h>

// =====================================================================
// RANSAC homography (JAX reference reproduction) for GB300 / sm_103a
// Fused design: one block per model does sample(alu) -> DLT(fp64, 8-thread
// warp-parallel) -> score(fma). Resident blocks at different phases keep
// both SM pipes busy simultaneously.
// =====================================================================

#define N_PTS    10000
#define BATCH    2048
#define MAX_ITER 10
#define NMODELS  (BATCH * MAX_ITER)
#define TPB      128

__device__ float g_H[NMODELS * 9];
__device__ float g_Hinv[NMODELS * 9];
__device__ int   g_best;   // packed (score<<15)|(32767-m); winner iff score>=2

struct KeyList { uint32_t k0[MAX_ITER]; uint32_t k1[MAX_ITER]; };

// -------- threefry2x32 core (matches jax._src.prng exactly) ----------
__host__ __device__ __forceinline__ void tf2x32(uint32_t k0, uint32_t k1,
                                                uint32_t x0, uint32_t x1,
                                                uint32_t& o0, uint32_t& o1) {
  const uint32_t ks2 = k0 ^ k1 ^ 0x1BD11BDAu;
  x0 += k0; x1 += k1;
#define TF_R(r) { x0 += x1; x1 = (x1 << (r)) | (x1 >> (32 - (r))); x1 ^= x0; }
  TF_R(13) TF_R(15) TF_R(26) TF_R(6)
  x0 += k1;  x1 += ks2 + 1u;
  TF_R(17) TF_R(29) TF_R(16) TF_R(24)
  x0 += ks2; x1 += k0 + 2u;
  TF_R(13) TF_R(15) TF_R(26) TF_R(6)
  x0 += k0;  x1 += k1 + 3u;
  TF_R(17) TF_R(29) TF_R(16) TF_R(24)
  x0 += k1;  x1 += ks2 + 4u;
  TF_R(13) TF_R(15) TF_R(26) TF_R(6)
  x0 += ks2; x1 += k0 + 5u;
#undef TF_R
  o0 = x0; o1 = x1;
}

// symmetric transfer error half (f32, identical to the passing version)
__device__ __forceinline__ float terr(const float* H, float x, float y,
                                      float qx, float qy) {
  float X = fmaf(H[0], x, fmaf(H[1], y, H[2]));
  float Y = fmaf(H[3], x, fmaf(H[4], y, H[5]));
  float Z = fmaf(H[6], x, fmaf(H[7], y, H[8]));
  float s = (fabsf(Z) > 1e-8f) ? __fdiv_rn(1.0f, Z) : 1.0f;
  float dx = fmaf(X, s, -qx);
  float dy = fmaf(Y, s, -qy);
  return fmaf(dx, dx, dy * dy);
}

__global__ void k_init() { g_best = 0; }

// =====================================================================
// Fused kernel: block = model m = it*BATCH + b
// =====================================================================
__global__ __launch_bounds__(TPB) void k_fused(KeyList keys,
                                               const float2* __restrict__ kp1,
                                               const float2* __restrict__ kp2) {
  const int m   = blockIdx.x;
  const int it  = m / BATCH;
  const int b   = m - it * BATCH;
  const int tid = threadIdx.x;

  __shared__ uint64_t sk[TPB][4];     // packed topk keys
  __shared__ float    sH[9], sHi[9];
  __shared__ int      sValid;
  __shared__ int      swred[TPB / 32];

  // ---------------- Phase 1: sample — exact top-4 of 10000 uniforms ---
  {
    const uint32_t kk0 = keys.k0[it];
    const uint32_t kk1 = keys.k1[it];
    const uint32_t base = (uint32_t)b * (uint32_t)N_PTS;

    uint64_t t0 = 0, t1 = 0, t2 = 0, t3 = 0;  // descending; 0 < any real key
#pragma unroll 2
    for (int j = tid; j < N_PTS; j += TPB) {
      uint32_t y0, y1;
      tf2x32(kk0, kk1, 0u, base + (uint32_t)j, y0, y1);
      uint32_t bits = y0 ^ y1;
      // pack: top-23 uniform bits desc, then index asc (matches lax.top_k)
      uint64_t key = ((uint64_t)(bits >> 9) << 14) | (uint32_t)(16383 - j);
      if (key > t3) {
        if (key > t0)      { t3 = t2; t2 = t1; t1 = t0; t0 = key; }
        else if (key > t1) { t3 = t2; t2 = t1; t1 = key; }
        else if (key > t2) { t3 = t2; t2 = key; }
        else               { t3 = key; }
      }
    }
    sk[tid][0] = t0; sk[tid][1] = t1; sk[tid][2] = t2; sk[tid][3] = t3;
    __syncthreads();
    for (int s = TPB / 2; s >= 1; s >>= 1) {
      if (tid < s) {
        uint64_t o[4];
        int pa = 0, pb = 0;
#pragma unroll
        for (int t = 0; t < 4; t++) {
          uint64_t av = sk[tid][pa], bv = sk[tid + s][pb];
          if (av > bv) { o[t] = av; pa++; } else { o[t] = bv; pb++; }
        }
#pragma unroll
        for (int t = 0; t < 4; t++) sk[tid][t] = o[t];
      }
      __syncthreads();
    }
  }

  // ---------------- Phase 2: DLT (8 threads, fp64, row-parallel) ------
  if (tid < 8) {
    const unsigned FULL = 0xffu;
    int idx[4];
#pragma unroll
    for (int t = 0; t < 4; t++) idx[t] = 16383 - (int)(sk[0][t] & 16383u);

    double px[4], py[4], qx[4], qy[4];
#pragma unroll
    for (int t = 0; t < 4; t++) {
      float2 p = kp1[idx[t]], q = kp2[idx[t]];
      px[t] = (double)p.x; py[t] = (double)p.y;
      qx[t] = (double)q.x; qy[t] = (double)q.y;
    }
    // normalize_points (fp64, identical arithmetic to passing version)
    double m1x = 0.25 * (px[0] + px[1] + px[2] + px[3]);
    double m1y = 0.25 * (py[0] + py[1] + py[2] + py[3]);
    double m2x = 0.25 * (qx[0] + qx[1] + qx[2] + qx[3]);
    double m2y = 0.25 * (qy[0] + qy[1] + qy[2] + qy[3]);
    double d1 = 0.0, d2 = 0.0;
#pragma unroll
    for (int t = 0; t < 4; t++) {
      double ax = px[t] - m1x, ay = py[t] - m1y;
      double bx = qx[t] - m2x, by = qy[t] - m2y;
      d1 += sqrt(ax * ax + ay * ay);
      d2 += sqrt(bx * bx + by * by);
    }
    d1 *= 0.25; d2 *= 0.25;
    const double SQ2 = 1.4142135623730951;
    double s1 = SQ2 / (d1 + 1e-8);
    double s2 = SQ2 / (d2 + 1e-8);

    // my row of A (threads 0-3: ax rows; 4-7: ay rows)
    int t4 = tid & 3;
    double xx = (px[t4] - m1x) * s1, yy = (py[t4] - m1y) * s1;
    double XX = (qx[t4] - m2x) * s2, YY = (qy[t4] - m2y) * s2;
    double A[9];
    if (tid < 4) {
      A[0] = 0.0;  A[1] = 0.0;  A[2] = 0.0;
      A[3] = -xx;  A[4] = -yy;  A[5] = -1.0;
      A[6] = YY * xx; A[7] = YY * yy; A[8] = YY;
    } else {
      A[0] = xx;   A[1] = yy;   A[2] = 1.0;
      A[3] = 0.0;  A[4] = 0.0;  A[5] = 0.0;
      A[6] = -XX * xx; A[7] = -XX * yy; A[8] = -XX;
    }

    // forward elimination with partial pivoting (cols 0..7)
    int my_piv = -1;
#pragma unroll
    for (int c = 0; c < 8; c++) {
      bool active = (my_piv < 0);
      double bestv = active ? fabs(A[c]) : -1.0;
      int bestl = tid;
#pragma unroll
      for (int o = 4; o; o >>= 1) {
        double ov = __shfl_xor_sync(FULL, bestv, o, 8);
        int    ol = __shfl_xor_sync(FULL, bestl, o, 8);
        if (ov > bestv || (ov == bestv && ol < bestl)) { bestv = ov; bestl = ol; }
      }
      int p = bestl;
      double pr[9];
#pragma unroll
      for (int j = 0; j < 9; j++) pr[j] = __shfl_sync(FULL, A[j], p, 8);
      if (tid == p) {
        my_piv = c;
      } else if (active) {
        double f = A[c] * (1.0 / pr[c]);
#pragma unroll
        for (int j = 0; j < 9; j++) A[j] -= f * pr[j];
      }
    }
    // back substitution; free column = 8, h replicated on all 8 lanes
    double h[9];
    h[8] = 1.0;
#pragma unroll
    for (int c = 7; c >= 0; c--) {
      double sacc = 0.0;
#pragma unroll
      for (int j = 8; j > c; j--) sacc += A[j] * h[j];
      // match sequential order (jj ascending) for bit-identical rounding:
      {
        double s2a = 0.0;
#pragma unroll
        for (int j = c + 1; j < 9; j++) s2a += A[j] * h[j];
        sacc = s2a;
      }
      double val = -sacc / A[c];
      unsigned msk = __ballot_sync(FULL, my_piv == c);
      int lane = __ffs(msk) - 1;
      h[c] = __shfl_sync(FULL, val, lane, 8);
    }

    if (tid == 0) {
      // unit-normalize
      double nrm = 0.0;
#pragma unroll
      for (int c = 0; c < 9; c++) nrm += h[c] * h[c];
      double inrm = 1.0 / sqrt(nrm);
#pragma unroll
      for (int c = 0; c < 9; c++) h[c] *= inrm;

      // H = inv(T2) * Hn * T1
      double M[9];
#pragma unroll
      for (int rr = 0; rr < 3; rr++) {
        double a = h[rr * 3 + 0], bb = h[rr * 3 + 1], cc = h[rr * 3 + 2];
        M[rr * 3 + 0] = a * s1;
        M[rr * 3 + 1] = bb * s1;
        M[rr * 3 + 2] = -a * s1 * m1x - bb * s1 * m1y + cc;
      }
      double Hd[9];
      double is2 = 1.0 / s2;
#pragma unroll
      for (int c = 0; c < 3; c++) {
        Hd[0 * 3 + c] = is2 * M[0 * 3 + c] + m2x * M[2 * 3 + c];
        Hd[1 * 3 + c] = is2 * M[1 * 3 + c] + m2y * M[2 * 3 + c];
        Hd[2 * 3 + c] = M[2 * 3 + c];
      }
      double dv = Hd[8] + 1e-8;
      float Hf[9];
#pragma unroll
      for (int c = 0; c < 9; c++) Hf[c] = (float)(Hd[c] / dv);

      bool valid = (fabsf(Hf[0]) > 1e-6f) && (fabsf(Hf[4]) > 1e-6f) &&
                   (fabsf(Hf[8]) > 1e-6f);

      // Hinv from the float32 H (fp64 adjugate)
      double a = Hf[0], bb = Hf[1], cc = Hf[2];
      double d = Hf[3], e = Hf[4],  f = Hf[5];
      double g = Hf[6], hh = Hf[7], ii = Hf[8];
      double A11 = e*ii - f*hh, A12 = cc*hh - bb*ii, A13 = bb*f - cc*e;
      double A21 = f*g  - d*ii, A22 = a*ii - cc*g,  A23 = cc*d - a*f;
      double A31 = d*hh - e*g,  A32 = bb*g - a*hh,  A33 = a*e - bb*d;
      double det  = a*A11 + bb*A21 + cc*A31;
      double idet = 1.0 / det;
      float Hif[9] = {(float)(A11*idet), (float)(A12*idet), (float)(A13*idet),
                      (float)(A21*idet), (float)(A22*idet), (float)(A23*idet),
                      (float)(A31*idet), (float)(A32*idet), (float)(A33*idet)};
#pragma unroll
      for (int c = 0; c < 9; c++) {
        sH[c]  = Hf[c];
        sHi[c] = Hif[c];
        g_H[m * 9 + c]    = Hf[c];
        g_Hinv[m * 9 + c] = Hif[c];
      }
      sValid = valid ? 1 : 0;
    }
  }
  __syncthreads();
  if (!sValid) return;   // uniform across block

  // ---------------- Phase 3: score (fma-heavy) ------------------------
  float H[9], Hi[9];
#pragma unroll
  for (int c = 0; c < 9; c++) { H[c] = sH[c]; Hi[c] = sHi[c]; }
  int cnt = 0;
#pragma unroll 2
  for (int j = tid; j < N_PTS; j += TPB) {
    float2 p = kp1[j], q = kp2[j];
    float e = terr(H, p.x, p.y, q.x, q.y) + terr(Hi, q.x, q.y, p.x, p.y);
    cnt += (e <= 2.0f) ? 1 : 0;
  }
#pragma unroll
  for (int o = 16; o; o >>= 1) cnt += __shfl_down_sync(0xffffffffu, cnt, o);
  if ((tid & 31) == 0) swred[tid >> 5] = cnt;
  __syncthreads();
  if (tid == 0) {
    int tot = swred[0] + swred[1] + swred[2] + swred[3];
    // pack: max score, tie -> smallest m (earlier iter, then lower batch idx)
    atomicMax(&g_best, (tot << 15) | (32767 - m));
  }
}

// =====================================================================
// Output: [H(9), inlier mask(10000)] float32
// =====================================================================
__global__ __launch_bounds__(256) void k_out(const float2* __restrict__ kp1,
                                             const float2* __restrict__ kp2,
                                             float* __restrict__ out,
                                             int out_size) {
  const int t = blockIdx.x * blockDim.x + threadIdx.x;
  if (t >= out_size) return;
  const int gb = g_best;
  const int best = ((gb >> 15) >= 2) ? (32767 - (gb & 32767)) : -1;
  if (t < 9) {
    out[t] = (best >= 0) ? g_H[best * 9 + t]
                         : ((t == 0 || t == 4 || t == 8) ? 1.0f : 0.0f);
  } else if (t < 9 + N_PTS) {
    int j = t - 9;
    float r = 0.0f;
    if (best >= 0) {
      float H[9], Hi[9];
#pragma unroll
      for (int c = 0; c < 9; c++) { H[c] = g_H[best*9+c]; Hi[c] = g_Hinv[best*9+c]; }
      float2 p = kp1[j], q = kp2[j];
      float e = terr(H, p.x, p.y, q.x, q.y) + terr(Hi, q.x, q.y, p.x, p.y);
      r = (e <= 2.0f) ? 1.0f : 0.0f;
    }
    out[t] = r;
  } else {
    out[t] = 0.0f;
  }
}

// =====================================================================
extern "C" void kernel_launch(void* const* d_in, const int* in_sizes, int n_in,
                              void* d_out, int out_size) {
  const float* kp1 = (const float*)d_in[0];
  const float* kp2 = (const float*)d_in[1];
  float* out = (float*)d_out;

  // iteration keys from jax.random.key(42), partitionable foldlike split
  KeyList keys;
  for (int j = 0; j < MAX_ITER; j++) {
    uint32_t a, b;
    tf2x32(0u, 42u, 0u, (uint32_t)j, a, b);
    keys.k0[j] = a; keys.k1[j] = b;
  }

  k_init<<<1, 1>>>();
  k_fused<<<NMODELS, TPB>>>(keys, (const float2*)kp1, (const float2*)kp2);
  int nt = out_size > 0 ? out_size : 1;
  k_out<<<(nt + 255) / 256, 256>>>((const float2*)kp1, (const float2*)kp2, out, out_size);
}